// round 8
// baseline (speedup 1.0000x reference)
#include <cuda_runtime.h>
#include <math.h>
#include <stdint.h>

#define DM   512
#define LSEQ 256
#define BB   2
#define HH   8
#define DK   64
#define BH   16
#define BL   512
#define NEG_BIG -1.0e30f
#define POS_BIG  1.0e30f

// ---------------- scratch (device globals; no allocations allowed) -----------
__device__ float g_actq[BL * DM];
__device__ float g_actk[BL * DM];
__device__ float g_actv[BL * DM];
__device__ float g_Q[BH * LSEQ * DK];
__device__ float g_K[BH * LSEQ * DK];
__device__ float g_V[BH * LSEQ * DK];
__device__ float g_ctx[BL * DM];
__device__ float g_op[4 * BL * DM];   // out-GEMM splitK partials

// ---------------- tf32 helpers ------------------------------------------------
__device__ __forceinline__ float tf32r(float x) {
    uint32_t u;
    asm("cvt.rna.tf32.f32 %0, %1;" : "=r"(u) : "f"(x));
    return __uint_as_float(u);
}
__device__ __forceinline__ void mma_tf32(float* d, const uint32_t* a, const uint32_t* b) {
    asm volatile(
        "mma.sync.aligned.m16n8k8.row.col.f32.tf32.tf32.f32 "
        "{%0,%1,%2,%3}, {%4,%5,%6,%7}, {%8,%9}, {%0,%1,%2,%3};"
        : "+f"(d[0]), "+f"(d[1]), "+f"(d[2]), "+f"(d[3])
        : "r"(a[0]), "r"(a[1]), "r"(a[2]), "r"(a[3]), "r"(b[0]), "r"(b[1]));
}

#define SROW 40   // smem row stride in floats ({hi,lo} x 16 k + pad)

// convert float4 -> two float4 {hi,lo,hi,lo} stores
__device__ __forceinline__ void cvt_store(float* base, int row, int kq, float4 v) {
    float h0 = tf32r(v.x), h1 = tf32r(v.y), h2 = tf32r(v.z), h3 = tf32r(v.w);
    float l0 = tf32r(v.x - h0), l1 = tf32r(v.y - h1);
    float l2 = tf32r(v.z - h2), l3 = tf32r(v.w - h3);
    *(float4*)&base[row * SROW + 2 * kq]     = make_float4(h0, l0, h1, l1);
    *(float4*)&base[row * SROW + 2 * kq + 4] = make_float4(h2, l2, h3, l3);
}

// ---------------- tensor-core GEMM: Y = X @ W^T (split-tf32, 3-mma) ----------
// 64x64 block tile, 256 threads = 8 warps (4 m-warps x 2 n-warps, warp 16x32).
// mode 0: proj (3 gemms, K=512), epilogue log1p(relu)-lam  grid (8,8,3)
// mode 1: out GEMM, splitK=4 (K=128/block) -> g_op partial grid (8,8,4)
__global__ __launch_bounds__(256) void k_gemm_tc(const float* __restrict__ Xin,
                                                 const float* __restrict__ W0,
                                                 const float* __restrict__ W1,
                                                 const float* __restrict__ W2,
                                                 const float* __restrict__ lam,
                                                 int mode)
{
    __shared__ float As[2][64 * SROW];
    __shared__ float Bs[2][64 * SROW];

    const int gemm = (mode == 0) ? (int)blockIdx.z : 0;
    const int zk   = (mode == 0) ? 0 : (int)blockIdx.z;
    const float* X = (mode == 0) ? Xin : g_ctx;
    const float* W = (gemm == 0) ? W0 : ((gemm == 1) ? W1 : W2);
    float* Y = (mode == 0)
        ? ((gemm == 0) ? g_actq : ((gemm == 1) ? g_actk : g_actv))
        : (g_op + zk * (BL * DM));
    const int k0 = zk * 128;
    const int nc = (mode == 0) ? 32 : 8;     // chunks of 16 k

    const int bm = blockIdx.y, bn = blockIdx.x;
    const int tid = threadIdx.x;
    const int wid = tid >> 5, lane = tid & 31;
    const int m0 = (wid & 3) * 16;           // warp m-offset
    const int n0 = (wid >> 2) * 32;          // warp n-offset
    const int g = lane >> 2, cc = lane & 3;
    const int lrow = tid >> 2, lkq = (tid & 3) * 4;   // loader mapping

    float acc[4][4];
#pragma unroll
    for (int nt = 0; nt < 4; nt++)
#pragma unroll
        for (int e = 0; e < 4; e++) acc[nt][e] = 0.0f;

    const float* Apt = &X[(bm * 64 + lrow) * DM + k0 + lkq];
    const float* Bpt = &W[(bn * 64 + lrow) * DM + k0 + lkq];

    float4 xa = *(const float4*)Apt;
    float4 wb = *(const float4*)Bpt;
    cvt_store(As[0], lrow, lkq, xa);
    cvt_store(Bs[0], lrow, lkq, wb);
    __syncthreads();

    for (int ch = 0; ch < nc; ch++) {
        const int cur = ch & 1, nxt = cur ^ 1;
        if (ch + 1 < nc) {
            xa = *(const float4*)(Apt + (ch + 1) * 16);
            wb = *(const float4*)(Bpt + (ch + 1) * 16);
        }
#pragma unroll
        for (int ks = 0; ks < 2; ks++) {
            const int kb = ks * 8;
            const float* Ab = As[cur];
            const float* Bb = Bs[cur];
            const float2 a0 = *(const float2*)&Ab[(m0 + g) * SROW + 2 * (kb + cc)];
            const float2 a1 = *(const float2*)&Ab[(m0 + g + 8) * SROW + 2 * (kb + cc)];
            const float2 a2 = *(const float2*)&Ab[(m0 + g) * SROW + 2 * (kb + cc + 4)];
            const float2 a3 = *(const float2*)&Ab[(m0 + g + 8) * SROW + 2 * (kb + cc + 4)];
            const uint32_t ahi[4] = {__float_as_uint(a0.x), __float_as_uint(a1.x),
                                     __float_as_uint(a2.x), __float_as_uint(a3.x)};
            const uint32_t alo[4] = {__float_as_uint(a0.y), __float_as_uint(a1.y),
                                     __float_as_uint(a2.y), __float_as_uint(a3.y)};
#pragma unroll
            for (int nt = 0; nt < 4; nt++) {
                const int n = n0 + nt * 8 + g;
                const float2 b0 = *(const float2*)&Bb[n * SROW + 2 * (kb + cc)];
                const float2 b1 = *(const float2*)&Bb[n * SROW + 2 * (kb + cc + 4)];
                const uint32_t bhi[2] = {__float_as_uint(b0.x), __float_as_uint(b1.x)};
                const uint32_t blo[2] = {__float_as_uint(b0.y), __float_as_uint(b1.y)};
                mma_tf32(acc[nt], ahi, bhi);
                mma_tf32(acc[nt], ahi, blo);
                mma_tf32(acc[nt], alo, bhi);
            }
        }
        if (ch + 1 < nc) {
            cvt_store(As[nxt], lrow, lkq, xa);
            cvt_store(Bs[nxt], lrow, lkq, wb);
            __syncthreads();
        }
    }

    // epilogue
    const int row0 = bm * 64 + m0 + g;
#pragma unroll
    for (int nt = 0; nt < 4; nt++) {
        const int col = bn * 64 + n0 + nt * 8 + cc * 2;
        float y0 = acc[nt][0], y1 = acc[nt][1];
        float y2 = acc[nt][2], y3 = acc[nt][3];
        if (mode == 0) {
            const float l0 = lam[col], l1 = lam[col + 1];
            y0 = log1pf(fmaxf(y0, 0.0f)) - l0;
            y1 = log1pf(fmaxf(y1, 0.0f)) - l1;
            y2 = log1pf(fmaxf(y2, 0.0f)) - l0;
            y3 = log1pf(fmaxf(y3, 0.0f)) - l1;
        }
        *(float2*)&Y[row0 * DM + col] = make_float2(y0, y1);
        *(float2*)&Y[(row0 + 8) * DM + col] = make_float2(y2, y3);
    }
}

// ---------------- tropical linear ---------------------------------------------
__global__ __launch_bounds__(256) void k_trop(const float* __restrict__ Wqt,
                                              const float* __restrict__ Wkt,
                                              const float* __restrict__ Wvt)
{
    __shared__ float Wts[64][65];   // transposed: Wts[i][o]
    __shared__ float ar[16][65];

    const int gemm = blockIdx.z;
    const float* Wt = (gemm == 0) ? Wqt : ((gemm == 1) ? Wkt : Wvt);
    const float* act = (gemm == 0) ? g_actq : ((gemm == 1) ? g_actk : g_actv);
    float* out = (gemm == 0) ? g_Q : ((gemm == 1) ? g_K : g_V);
    const int bh = blockIdx.y;
    const int b = bh >> 3, h = bh & 7;
    const int l0 = blockIdx.x * 16;
    const int tid = threadIdx.x;

    for (int idx = tid; idx < 64 * 64; idx += 256) {
        const int o = idx >> 6, i = idx & 63;
        Wts[i][o] = Wt[idx];
    }
    for (int idx = tid; idx < 16 * 64; idx += 256) {
        const int r = idx >> 6, i = idx & 63;
        ar[r][i] = act[(b * LSEQ + l0 + r) * DM + h * DK + i];
    }
    __syncthreads();

    const int o = tid & 63, rg = tid >> 6;
    float m[4] = {NEG_BIG, NEG_BIG, NEG_BIG, NEG_BIG};
#pragma unroll 8
    for (int i = 0; i < 64; i++) {
        const float wv = Wts[i][o];
#pragma unroll
        for (int rr = 0; rr < 4; rr++)
            m[rr] = fmaxf(m[rr], ar[rg * 4 + rr][i] + wv);
    }
#pragma unroll
    for (int rr = 0; rr < 4; rr++)
        out[(bh * LSEQ + l0 + rg * 4 + rr) * DK + o] = m[rr];
}

// ---------------- fused tropical attention ------------------------------------
__global__ __launch_bounds__(256, 4) void k_attn(float* __restrict__ scores)
{
    __shared__ float Qs[8][68];
    __shared__ float Ks[64][68];
    __shared__ float Vs[64][68];
    __shared__ float Ss[64][9];

    const int bh = blockIdx.y;
    const int it = blockIdx.x;        // 0..31
    const int i0 = it * 8;
    const int b = bh >> 3, h = bh & 7;
    const int tid = threadIdx.x;
    const int lane = tid & 31;
    const int w  = tid >> 5;          // warp 0..7 = phase-B i row
    const int ii = tid & 7;           // phase-A i
    const int jg = tid >> 3;          // phase-A j-group (0..31), 2 j each

    if (tid < 128) {
        const int r = tid >> 4, dq = (tid & 15) * 4;
        *(float4*)&Qs[r][dq] = *(const float4*)&g_Q[(bh * LSEQ + i0 + r) * DK + dq];
    }

    float accE0 = NEG_BIG, accE1 = NEG_BIG;
    float accO0 = NEG_BIG, accO1 = NEG_BIG;

    for (int cch = 0; cch < 4; cch++) {
        const float4* Kp = (const float4*)(g_K + (bh * LSEQ + cch * 64) * DK);
        const float4* Vp = (const float4*)(g_V + (bh * LSEQ + cch * 64) * DK);
        for (int idx = tid; idx < 1024; idx += 256) {
            const int j = idx >> 4, dq = (idx & 15) * 4;
            *(float4*)&Ks[j][dq] = Kp[idx];
            *(float4*)&Vs[j][dq] = Vp[idx];
        }
        __syncthreads();

        // ---- phase A: scores for 2 j per thread ----
        {
            const int j0 = jg * 2;
            float mxa[2] = {NEG_BIG, NEG_BIG}, mxb[2] = {NEG_BIG, NEG_BIG};
            float mna[2] = {POS_BIG, POS_BIG}, mnb[2] = {POS_BIG, POS_BIG};
#pragma unroll
            for (int t = 0; t < 16; t++) {
                const float4 q4 = *(const float4*)&Qs[ii][t * 4];
#pragma unroll
                for (int jj = 0; jj < 2; jj++) {
                    const float4 k4 = *(const float4*)&Ks[j0 + jj][t * 4];
                    const float d0 = q4.x - k4.x;
                    const float d1 = q4.y - k4.y;
                    const float d2 = q4.z - k4.z;
                    const float d3 = q4.w - k4.w;
                    mxa[jj] = fmaxf(mxa[jj], d0); mna[jj] = fminf(mna[jj], d0);
                    mxb[jj] = fmaxf(mxb[jj], d1); mnb[jj] = fminf(mnb[jj], d1);
                    mxa[jj] = fmaxf(mxa[jj], d2); mna[jj] = fminf(mna[jj], d2);
                    mxb[jj] = fmaxf(mxb[jj], d3); mnb[jj] = fminf(mnb[jj], d3);
                }
            }
#pragma unroll
            for (int jj = 0; jj < 2; jj++) {
                const float sc = fminf(mna[jj], mnb[jj]) - fmaxf(mxa[jj], mxb[jj]);
                Ss[j0 + jj][ii] = sc;
                scores[(bh * LSEQ + i0 + ii) * LSEQ + cch * 64 + j0 + jj] = sc;
            }
        }
        __syncthreads();

        // ---- phase B: context (warp = i row, d across lanes, j serial) ----
#pragma unroll 4
        for (int j = 0; j < 64; j += 2) {
            const float sE = Ss[j][w];
            const float sO = Ss[j + 1][w];
            const float2 vE = *(const float2*)&Vs[j][lane * 2];
            const float2 vO = *(const float2*)&Vs[j + 1][lane * 2];
            accE0 = fmaxf(accE0, sE + vE.x);
            accE1 = fmaxf(accE1, sE + vE.y);
            accO0 = fmaxf(accO0, sO + vO.x);
            accO1 = fmaxf(accO1, sO + vO.y);
        }
        __syncthreads();
    }

    {
        const int l = i0 + w;
        float2 v;
        v.x = expm1f(fmaxf(accE0, accO0));
        v.y = expm1f(fmaxf(accE1, accO1));
        *(float2*)&g_ctx[(b * LSEQ + l) * DM + h * DK + lane * 2] = v;
    }
}

// ---------------- splitK reduce for the output GEMM ---------------------------
__global__ __launch_bounds__(256) void k_reduce(float* __restrict__ out)
{
    const int idx = blockIdx.x * 256 + threadIdx.x;   // float4 index, 65536 total
    const float4* p = (const float4*)g_op;
    float4 s = p[idx];
#pragma unroll
    for (int z = 1; z < 4; z++) {
        const float4 t = p[z * 65536 + idx];
        s.x += t.x; s.y += t.y; s.z += t.z; s.w += t.w;
    }
    ((float4*)out)[idx] = s;
}

// ---------------- launch ------------------------------------------------------
extern "C" void kernel_launch(void* const* d_in, const int* in_sizes, int n_in,
                              void* d_out, int out_size)
{
    const float* x   = (const float*)d_in[0];
    const float* Wq  = (const float*)d_in[1];
    const float* Wk  = (const float*)d_in[2];
    const float* Wv  = (const float*)d_in[3];
    const float* Wo  = (const float*)d_in[4];
    const float* lam = (const float*)d_in[5];
    const float* Wqt = (const float*)d_in[6];
    const float* Wkt = (const float*)d_in[7];
    const float* Wvt = (const float*)d_in[8];
    float* out = (float*)d_out;
    float* scores = out + BL * DM;   // (output, attn_scores) flattened in order

    k_gemm_tc<<<dim3(8, 8, 3), 256>>>(x, Wq, Wk, Wv, lam, 0);   // projections
    k_trop<<<dim3(16, 16, 3), 256>>>(Wqt, Wkt, Wvt);            // tropical linears
    k_attn<<<dim3(32, 16), 256>>>(scores);                      // scores+context
    k_gemm_tc<<<dim3(8, 8, 4), 256>>>(nullptr, Wo, nullptr, nullptr,
                                      nullptr, 1);              // out GEMM splitK=4
    k_reduce<<<256, 256>>>(out);                                // reduce partials
}

// round 9
// speedup vs baseline: 1.1380x; 1.1380x over previous
#include <cuda_runtime.h>
#include <math.h>
#include <stdint.h>

#define DM   512
#define LSEQ 256
#define BB   2
#define HH   8
#define DK   64
#define BH   16
#define BL   512
#define NEG_BIG -1.0e30f
#define POS_BIG  1.0e30f

// ---------------- scratch (device globals; no allocations allowed) -----------
__device__ float2 g_xs[BL * DM];     // tf32-split {hi,lo} of x
__device__ float2 g_wqs[DM * DM];
__device__ float2 g_wks[DM * DM];
__device__ float2 g_wvs[DM * DM];
__device__ float2 g_wos[DM * DM];
__device__ float2 g_ctxs[BL * DM];   // split ctx (written by k_attn)
__device__ float  g_pp[6 * BL * DM]; // proj partials (3 gemms x splitK=2)
__device__ float  g_op[4 * BL * DM]; // out partials (splitK=4)
__device__ float  g_Q[BH * LSEQ * DK];
__device__ float  g_K[BH * LSEQ * DK];
__device__ float  g_V[BH * LSEQ * DK];

// ---------------- helpers -----------------------------------------------------
__device__ __forceinline__ float tf32r(float x) {
    uint32_t u;
    asm("cvt.rna.tf32.f32 %0, %1;" : "=r"(u) : "f"(x));
    return __uint_as_float(u);
}
__device__ __forceinline__ void mma_tf32(float* d, const uint32_t* a, const uint32_t* b) {
    asm volatile(
        "mma.sync.aligned.m16n8k8.row.col.f32.tf32.tf32.f32 "
        "{%0,%1,%2,%3}, {%4,%5,%6,%7}, {%8,%9}, {%0,%1,%2,%3};"
        : "+f"(d[0]), "+f"(d[1]), "+f"(d[2]), "+f"(d[3])
        : "r"(a[0]), "r"(a[1]), "r"(a[2]), "r"(a[3]), "r"(b[0]), "r"(b[1]));
}
__device__ __forceinline__ void cpasync16(uint32_t dst, const void* src) {
    asm volatile("cp.async.cg.shared.global [%0], [%1], 16;" :: "r"(dst), "l"(src));
}

// ---------------- prepass: tf32 split of x and the 4 weight matrices ----------
__global__ __launch_bounds__(256) void k_split(const float* __restrict__ x,
                                               const float* __restrict__ Wq,
                                               const float* __restrict__ Wk,
                                               const float* __restrict__ Wv,
                                               const float* __restrict__ Wo)
{
    const float* src;
    float2* dst;
    switch (blockIdx.y) {
        case 0: src = x;  dst = g_xs;  break;
        case 1: src = Wq; dst = g_wqs; break;
        case 2: src = Wk; dst = g_wks; break;
        case 3: src = Wv; dst = g_wvs; break;
        default: src = Wo; dst = g_wos; break;
    }
    const int base = (blockIdx.x * 256 + threadIdx.x) * 8;
#pragma unroll
    for (int t = 0; t < 2; t++) {
        const float4 v = *(const float4*)&src[base + t * 4];
        const float h0 = tf32r(v.x), h1 = tf32r(v.y), h2 = tf32r(v.z), h3 = tf32r(v.w);
        float4* d4 = (float4*)&dst[base + t * 4];
        d4[0] = make_float4(h0, tf32r(v.x - h0), h1, tf32r(v.y - h1));
        d4[1] = make_float4(h2, tf32r(v.z - h2), h3, tf32r(v.w - h3));
    }
}

// ---------------- TC GEMM: split-tf32 3-mma, cp.async 3-stage pipeline -------
// 64x64 tile, 256 threads = 8 warps (4 m x 2 n, warp 16x32), chunk = 16 k.
// mode 0: proj, z = gemm*2+zk (splitK=2, 256 k each) grid (8,8,6) -> g_pp
// mode 1: out,  z = zk        (splitK=4, 128 k each) grid (8,8,4) -> g_op
__global__ __launch_bounds__(256, 3) void k_gemm_tc(int mode)
{
    __shared__ float As[3][64 * 32];   // pad-free, XOR-swizzled; 8KB/stage
    __shared__ float Bs[3][64 * 32];

    const int z = blockIdx.z;
    const int gemm = (mode == 0) ? (z >> 1) : 0;
    const int zk   = (mode == 0) ? (z & 1) : z;
    const int k0   = (mode == 0) ? zk * 256 : zk * 128;
    const int nc   = (mode == 0) ? 16 : 8;
    const float2* Xs = (mode == 0) ? g_xs : g_ctxs;
    const float2* Ws = (mode == 0)
        ? ((gemm == 0) ? g_wqs : ((gemm == 1) ? g_wks : g_wvs)) : g_wos;
    float* Y = (mode == 0) ? (g_pp + z * (BL * DM)) : (g_op + z * (BL * DM));

    const int bm = blockIdx.y, bn = blockIdx.x;
    const int tid = threadIdx.x;
    const int wid = tid >> 5, lane = tid & 31;
    const int m0 = (wid & 3) * 16;
    const int n0 = (wid >> 2) * 32;
    const int g = lane >> 2, cc = lane & 3;
    const int sw = (g & 3) << 2;

    // loader mapping: row 0..63, two 16B units per operand
    const int lrow = tid >> 2, lq = tid & 3;
    const int usw0 = (lq) ^ ((lrow & 3) << 1);
    const int usw1 = (lq + 4) ^ ((lrow & 3) << 1);
    const float2* Xrow = &Xs[(bm * 64 + lrow) * DM + k0];
    const float2* Wrow = &Ws[(bn * 64 + lrow) * DM + k0];
    const uint32_t asb = (uint32_t)__cvta_generic_to_shared(&As[0][0]);
    const uint32_t bsb = (uint32_t)__cvta_generic_to_shared(&Bs[0][0]);

#define ISSUE_CHUNK(CH, BUF) do {                                            \
        const uint32_t ab = asb + (BUF) * 8192 + lrow * 128;                 \
        const uint32_t bb = bsb + (BUF) * 8192 + lrow * 128;                 \
        cpasync16(ab + usw0 * 16, Xrow + (CH) * 16 + lq * 2);                \
        cpasync16(ab + usw1 * 16, Xrow + (CH) * 16 + (lq + 4) * 2);          \
        cpasync16(bb + usw0 * 16, Wrow + (CH) * 16 + lq * 2);                \
        cpasync16(bb + usw1 * 16, Wrow + (CH) * 16 + (lq + 4) * 2);          \
        asm volatile("cp.async.commit_group;");                              \
    } while (0)

    float acc[4][4];
#pragma unroll
    for (int nt = 0; nt < 4; nt++)
#pragma unroll
        for (int e = 0; e < 4; e++) acc[nt][e] = 0.0f;

    ISSUE_CHUNK(0, 0);
    ISSUE_CHUNK(1, 1);

    for (int ch = 0; ch < nc; ch++) {
        if (ch + 1 < nc) { asm volatile("cp.async.wait_group 1;"); }
        else             { asm volatile("cp.async.wait_group 0;"); }
        __syncthreads();

        const float* Ab = As[ch % 3];
        const float* Bb = Bs[ch % 3];
#pragma unroll
        for (int ks = 0; ks < 2; ks++) {
            const int kb = ks * 8;
            const float2 a0 = *(const float2*)&Ab[(m0 + g) * 32 + 2 * ((kb + cc) ^ sw)];
            const float2 a1 = *(const float2*)&Ab[(m0 + g + 8) * 32 + 2 * ((kb + cc) ^ sw)];
            const float2 a2 = *(const float2*)&Ab[(m0 + g) * 32 + 2 * ((kb + cc + 4) ^ sw)];
            const float2 a3 = *(const float2*)&Ab[(m0 + g + 8) * 32 + 2 * ((kb + cc + 4) ^ sw)];
            const uint32_t ahi[4] = {__float_as_uint(a0.x), __float_as_uint(a1.x),
                                     __float_as_uint(a2.x), __float_as_uint(a3.x)};
            const uint32_t alo[4] = {__float_as_uint(a0.y), __float_as_uint(a1.y),
                                     __float_as_uint(a2.y), __float_as_uint(a3.y)};
#pragma unroll
            for (int nt = 0; nt < 4; nt++) {
                const int rn = n0 + nt * 8 + g;
                const float2 b0 = *(const float2*)&Bb[rn * 32 + 2 * ((kb + cc) ^ sw)];
                const float2 b1 = *(const float2*)&Bb[rn * 32 + 2 * ((kb + cc + 4) ^ sw)];
                const uint32_t bhi[2] = {__float_as_uint(b0.x), __float_as_uint(b1.x)};
                const uint32_t blo[2] = {__float_as_uint(b0.y), __float_as_uint(b1.y)};
                mma_tf32(acc[nt], ahi, bhi);
                mma_tf32(acc[nt], ahi, blo);
                mma_tf32(acc[nt], alo, bhi);
            }
        }
        __syncthreads();
        if (ch + 2 < nc) ISSUE_CHUNK(ch + 2, (ch + 2) % 3);
    }

    // epilogue: plain partial store
    const int row0 = bm * 64 + m0 + g;
#pragma unroll
    for (int nt = 0; nt < 4; nt++) {
        const int col = bn * 64 + n0 + nt * 8 + cc * 2;
        *(float2*)&Y[row0 * DM + col] = make_float2(acc[nt][0], acc[nt][1]);
        *(float2*)&Y[(row0 + 8) * DM + col] = make_float2(acc[nt][2], acc[nt][3]);
    }
#undef ISSUE_CHUNK
}

// ---------------- tropical linear + partial reduce + activation ---------------
__global__ __launch_bounds__(256) void k_trop(const float* __restrict__ Wqt,
                                              const float* __restrict__ Wkt,
                                              const float* __restrict__ Wvt,
                                              const float* __restrict__ lam)
{
    __shared__ float Wts[64][65];   // transposed: Wts[i][o]
    __shared__ float ar[16][65];

    const int gemm = blockIdx.z;
    const float* Wt = (gemm == 0) ? Wqt : ((gemm == 1) ? Wkt : Wvt);
    float* out = (gemm == 0) ? g_Q : ((gemm == 1) ? g_K : g_V);
    const int bh = blockIdx.y;
    const int b = bh >> 3, h = bh & 7;
    const int l0 = blockIdx.x * 16;
    const int tid = threadIdx.x;

    for (int idx = tid; idx < 64 * 64; idx += 256) {
        const int o = idx >> 6, i = idx & 63;
        Wts[i][o] = Wt[idx];
    }
    for (int idx = tid; idx < 16 * 64; idx += 256) {
        const int r = idx >> 6, i = idx & 63;
        const int gidx = (b * LSEQ + l0 + r) * DM + h * DK + i;
        const float* p = g_pp + gemm * 2 * (BL * DM) + gidx;
        const float s = p[0] + p[BL * DM];
        ar[r][i] = log1pf(fmaxf(s, 0.0f)) - lam[h * DK + i];
    }
    __syncthreads();

    const int o = tid & 63, rg = tid >> 6;
    float m[4] = {NEG_BIG, NEG_BIG, NEG_BIG, NEG_BIG};
#pragma unroll 8
    for (int i = 0; i < 64; i++) {
        const float wv = Wts[i][o];
#pragma unroll
        for (int rr = 0; rr < 4; rr++)
            m[rr] = fmaxf(m[rr], ar[rg * 4 + rr][i] + wv);
    }
#pragma unroll
    for (int rr = 0; rr < 4; rr++)
        out[(bh * LSEQ + l0 + rg * 4 + rr) * DK + o] = m[rr];
}

// ---------------- fused tropical attention (writes split ctx) -----------------
__global__ __launch_bounds__(256, 4) void k_attn(float* __restrict__ scores)
{
    __shared__ float Qs[8][68];
    __shared__ float Ks[64][68];
    __shared__ float Vs[64][68];
    __shared__ float Ss[64][9];

    const int bh = blockIdx.y;
    const int it = blockIdx.x;        // 0..31
    const int i0 = it * 8;
    const int b = bh >> 3, h = bh & 7;
    const int tid = threadIdx.x;
    const int lane = tid & 31;
    const int w  = tid >> 5;          // warp 0..7 = phase-B i row
    const int ii = tid & 7;           // phase-A i
    const int jg = tid >> 3;          // phase-A j-group (0..31), 2 j each

    if (tid < 128) {
        const int r = tid >> 4, dq = (tid & 15) * 4;
        *(float4*)&Qs[r][dq] = *(const float4*)&g_Q[(bh * LSEQ + i0 + r) * DK + dq];
    }

    float accE0 = NEG_BIG, accE1 = NEG_BIG;
    float accO0 = NEG_BIG, accO1 = NEG_BIG;

    for (int cch = 0; cch < 4; cch++) {
        const float4* Kp = (const float4*)(g_K + (bh * LSEQ + cch * 64) * DK);
        const float4* Vp = (const float4*)(g_V + (bh * LSEQ + cch * 64) * DK);
        for (int idx = tid; idx < 1024; idx += 256) {
            const int j = idx >> 4, dq = (idx & 15) * 4;
            *(float4*)&Ks[j][dq] = Kp[idx];
            *(float4*)&Vs[j][dq] = Vp[idx];
        }
        __syncthreads();

        // ---- phase A: scores for 2 j per thread ----
        {
            const int j0 = jg * 2;
            float mxa[2] = {NEG_BIG, NEG_BIG}, mxb[2] = {NEG_BIG, NEG_BIG};
            float mna[2] = {POS_BIG, POS_BIG}, mnb[2] = {POS_BIG, POS_BIG};
#pragma unroll
            for (int t = 0; t < 16; t++) {
                const float4 q4 = *(const float4*)&Qs[ii][t * 4];
#pragma unroll
                for (int jj = 0; jj < 2; jj++) {
                    const float4 k4 = *(const float4*)&Ks[j0 + jj][t * 4];
                    const float d0 = q4.x - k4.x;
                    const float d1 = q4.y - k4.y;
                    const float d2 = q4.z - k4.z;
                    const float d3 = q4.w - k4.w;
                    mxa[jj] = fmaxf(mxa[jj], d0); mna[jj] = fminf(mna[jj], d0);
                    mxb[jj] = fmaxf(mxb[jj], d1); mnb[jj] = fminf(mnb[jj], d1);
                    mxa[jj] = fmaxf(mxa[jj], d2); mna[jj] = fminf(mna[jj], d2);
                    mxb[jj] = fmaxf(mxb[jj], d3); mnb[jj] = fminf(mnb[jj], d3);
                }
            }
#pragma unroll
            for (int jj = 0; jj < 2; jj++) {
                const float sc = fminf(mna[jj], mnb[jj]) - fmaxf(mxa[jj], mxb[jj]);
                Ss[j0 + jj][ii] = sc;
                scores[(bh * LSEQ + i0 + ii) * LSEQ + cch * 64 + j0 + jj] = sc;
            }
        }
        __syncthreads();

        // ---- phase B: context ----
#pragma unroll 4
        for (int j = 0; j < 64; j += 2) {
            const float sE = Ss[j][w];
            const float sO = Ss[j + 1][w];
            const float2 vE = *(const float2*)&Vs[j][lane * 2];
            const float2 vO = *(const float2*)&Vs[j + 1][lane * 2];
            accE0 = fmaxf(accE0, sE + vE.x);
            accE1 = fmaxf(accE1, sE + vE.y);
            accO0 = fmaxf(accO0, sO + vO.x);
            accO1 = fmaxf(accO1, sO + vO.y);
        }
        __syncthreads();
    }

    {
        const int l = i0 + w;
        const float vx = expm1f(fmaxf(accE0, accO0));
        const float vy = expm1f(fmaxf(accE1, accO1));
        const float hx = tf32r(vx), hy = tf32r(vy);
        float4 pack = make_float4(hx, tf32r(vx - hx), hy, tf32r(vy - hy));
        *(float4*)&g_ctxs[(b * LSEQ + l) * DM + h * DK + lane * 2] = pack;
    }
}

// ---------------- splitK reduce for the output GEMM ---------------------------
__global__ __launch_bounds__(256) void k_reduce(float* __restrict__ out)
{
    const int idx = blockIdx.x * 256 + threadIdx.x;   // float4 index, 65536 total
    const float4* p = (const float4*)g_op;
    float4 s = p[idx];
#pragma unroll
    for (int z = 1; z < 4; z++) {
        const float4 t = p[z * 65536 + idx];
        s.x += t.x; s.y += t.y; s.z += t.z; s.w += t.w;
    }
    ((float4*)out)[idx] = s;
}

// ---------------- launch ------------------------------------------------------
extern "C" void kernel_launch(void* const* d_in, const int* in_sizes, int n_in,
                              void* d_out, int out_size)
{
    const float* x   = (const float*)d_in[0];
    const float* Wq  = (const float*)d_in[1];
    const float* Wk  = (const float*)d_in[2];
    const float* Wv  = (const float*)d_in[3];
    const float* Wo  = (const float*)d_in[4];
    const float* lam = (const float*)d_in[5];
    const float* Wqt = (const float*)d_in[6];
    const float* Wkt = (const float*)d_in[7];
    const float* Wvt = (const float*)d_in[8];
    float* out = (float*)d_out;
    float* scores = out + BL * DM;   // (output, attn_scores) flattened in order

    k_split<<<dim3(128, 5), 256>>>(x, Wq, Wk, Wv, Wo);      // tf32-split prepass
    k_gemm_tc<<<dim3(8, 8, 6), 256>>>(0);                   // projections (splitK=2)
    k_trop<<<dim3(16, 16, 3), 256>>>(Wqt, Wkt, Wvt, lam);   // reduce+activate+tropical
    k_attn<<<dim3(32, 16), 256>>>(scores);                  // scores+context (split ctx)
    k_gemm_tc<<<dim3(8, 8, 4), 256>>>(1);                   // out GEMM (splitK=4)
    k_reduce<<<256, 256>>>(out);                            // reduce partials
}

// round 10
// speedup vs baseline: 1.2577x; 1.1052x over previous
#include <cuda_runtime.h>
#include <math.h>
#include <stdint.h>

#define DM   512
#define LSEQ 256
#define BB   2
#define HH   8
#define DK   64
#define BH   16
#define BL   512
#define NEG_BIG -1.0e30f
#define POS_BIG  1.0e30f

// ---------------- scratch (device globals; no allocations allowed) -----------
__device__ float2 g_xs[BL * DM];     // tf32-split {hi,lo} of x
__device__ float2 g_wqs[DM * DM];
__device__ float2 g_wks[DM * DM];
__device__ float2 g_wvs[DM * DM];
__device__ float2 g_wos[DM * DM];
__device__ float2 g_ctxs[BL * DM];   // split ctx (written by k_attn)
__device__ float  g_pp[6 * BL * DM]; // proj partials (3 gemms x splitK=2)
__device__ float  g_op[4 * BL * DM]; // out partials (splitK=4)
__device__ float  g_Q[BH * LSEQ * DK];
__device__ float  g_K[BH * LSEQ * DK];
__device__ float  g_V[BH * LSEQ * DK];

// ---------------- helpers -----------------------------------------------------
__device__ __forceinline__ float tf32r(float x) {
    uint32_t u;
    asm("cvt.rna.tf32.f32 %0, %1;" : "=r"(u) : "f"(x));
    return __uint_as_float(u);
}
__device__ __forceinline__ void mma_tf32(float* d, const uint32_t* a, const uint32_t* b) {
    asm volatile(
        "mma.sync.aligned.m16n8k8.row.col.f32.tf32.tf32.f32 "
        "{%0,%1,%2,%3}, {%4,%5,%6,%7}, {%8,%9}, {%0,%1,%2,%3};"
        : "+f"(d[0]), "+f"(d[1]), "+f"(d[2]), "+f"(d[3])
        : "r"(a[0]), "r"(a[1]), "r"(a[2]), "r"(a[3]), "r"(b[0]), "r"(b[1]));
}
__device__ __forceinline__ void cpasync16(uint32_t dst, const void* src) {
    asm volatile("cp.async.cg.shared.global [%0], [%1], 16;" :: "r"(dst), "l"(src));
}

// ---------------- prepass: tf32 split of x and the 4 weight matrices ----------
__global__ __launch_bounds__(256) void k_split(const float* __restrict__ x,
                                               const float* __restrict__ Wq,
                                               const float* __restrict__ Wk,
                                               const float* __restrict__ Wv,
                                               const float* __restrict__ Wo)
{
    const float* src;
    float2* dst;
    switch (blockIdx.y) {
        case 0: src = x;  dst = g_xs;  break;
        case 1: src = Wq; dst = g_wqs; break;
        case 2: src = Wk; dst = g_wks; break;
        case 3: src = Wv; dst = g_wvs; break;
        default: src = Wo; dst = g_wos; break;
    }
    const int base = (blockIdx.x * 256 + threadIdx.x) * 8;
#pragma unroll
    for (int t = 0; t < 2; t++) {
        const float4 v = *(const float4*)&src[base + t * 4];
        const float h0 = tf32r(v.x), h1 = tf32r(v.y), h2 = tf32r(v.z), h3 = tf32r(v.w);
        float4* d4 = (float4*)&dst[base + t * 4];
        d4[0] = make_float4(h0, tf32r(v.x - h0), h1, tf32r(v.y - h1));
        d4[1] = make_float4(h2, tf32r(v.z - h2), h3, tf32r(v.w - h3));
    }
}

// ---------------- TC GEMM: split-tf32 3-mma, cp.async 3-stage pipeline -------
__global__ __launch_bounds__(256, 3) void k_gemm_tc(int mode)
{
    __shared__ float As[3][64 * 32];
    __shared__ float Bs[3][64 * 32];

    const int z = blockIdx.z;
    const int gemm = (mode == 0) ? (z >> 1) : 0;
    const int zk   = (mode == 0) ? (z & 1) : z;
    const int k0   = (mode == 0) ? zk * 256 : zk * 128;
    const int nc   = (mode == 0) ? 16 : 8;
    const float2* Xs = (mode == 0) ? g_xs : g_ctxs;
    const float2* Ws = (mode == 0)
        ? ((gemm == 0) ? g_wqs : ((gemm == 1) ? g_wks : g_wvs)) : g_wos;
    float* Y = (mode == 0) ? (g_pp + z * (BL * DM)) : (g_op + z * (BL * DM));

    const int bm = blockIdx.y, bn = blockIdx.x;
    const int tid = threadIdx.x;
    const int wid = tid >> 5, lane = tid & 31;
    const int m0 = (wid & 3) * 16;
    const int n0 = (wid >> 2) * 32;
    const int g = lane >> 2, cc = lane & 3;
    const int sw = (g & 3) << 2;

    const int lrow = tid >> 2, lq = tid & 3;
    const int usw0 = (lq) ^ ((lrow & 3) << 1);
    const int usw1 = (lq + 4) ^ ((lrow & 3) << 1);
    const float2* Xrow = &Xs[(bm * 64 + lrow) * DM + k0];
    const float2* Wrow = &Ws[(bn * 64 + lrow) * DM + k0];
    const uint32_t asb = (uint32_t)__cvta_generic_to_shared(&As[0][0]);
    const uint32_t bsb = (uint32_t)__cvta_generic_to_shared(&Bs[0][0]);

#define ISSUE_CHUNK(CH, BUF) do {                                            \
        const uint32_t ab = asb + (BUF) * 8192 + lrow * 128;                 \
        const uint32_t bb = bsb + (BUF) * 8192 + lrow * 128;                 \
        cpasync16(ab + usw0 * 16, Xrow + (CH) * 16 + lq * 2);                \
        cpasync16(ab + usw1 * 16, Xrow + (CH) * 16 + (lq + 4) * 2);          \
        cpasync16(bb + usw0 * 16, Wrow + (CH) * 16 + lq * 2);                \
        cpasync16(bb + usw1 * 16, Wrow + (CH) * 16 + (lq + 4) * 2);          \
        asm volatile("cp.async.commit_group;");                              \
    } while (0)

    float acc[4][4];
#pragma unroll
    for (int nt = 0; nt < 4; nt++)
#pragma unroll
        for (int e = 0; e < 4; e++) acc[nt][e] = 0.0f;

    ISSUE_CHUNK(0, 0);
    ISSUE_CHUNK(1, 1);

    for (int ch = 0; ch < nc; ch++) {
        if (ch + 1 < nc) { asm volatile("cp.async.wait_group 1;"); }
        else             { asm volatile("cp.async.wait_group 0;"); }
        __syncthreads();

        const float* Ab = As[ch % 3];
        const float* Bb = Bs[ch % 3];
#pragma unroll
        for (int ks = 0; ks < 2; ks++) {
            const int kb = ks * 8;
            const float2 a0 = *(const float2*)&Ab[(m0 + g) * 32 + 2 * ((kb + cc) ^ sw)];
            const float2 a1 = *(const float2*)&Ab[(m0 + g + 8) * 32 + 2 * ((kb + cc) ^ sw)];
            const float2 a2 = *(const float2*)&Ab[(m0 + g) * 32 + 2 * ((kb + cc + 4) ^ sw)];
            const float2 a3 = *(const float2*)&Ab[(m0 + g + 8) * 32 + 2 * ((kb + cc + 4) ^ sw)];
            const uint32_t ahi[4] = {__float_as_uint(a0.x), __float_as_uint(a1.x),
                                     __float_as_uint(a2.x), __float_as_uint(a3.x)};
            const uint32_t alo[4] = {__float_as_uint(a0.y), __float_as_uint(a1.y),
                                     __float_as_uint(a2.y), __float_as_uint(a3.y)};
#pragma unroll
            for (int nt = 0; nt < 4; nt++) {
                const int rn = n0 + nt * 8 + g;
                const float2 b0 = *(const float2*)&Bb[rn * 32 + 2 * ((kb + cc) ^ sw)];
                const float2 b1 = *(const float2*)&Bb[rn * 32 + 2 * ((kb + cc + 4) ^ sw)];
                const uint32_t bhi[2] = {__float_as_uint(b0.x), __float_as_uint(b1.x)};
                const uint32_t blo[2] = {__float_as_uint(b0.y), __float_as_uint(b1.y)};
                mma_tf32(acc[nt], ahi, bhi);
                mma_tf32(acc[nt], ahi, blo);
                mma_tf32(acc[nt], alo, bhi);
            }
        }
        __syncthreads();
        if (ch + 2 < nc) ISSUE_CHUNK(ch + 2, (ch + 2) % 3);
    }

    const int row0 = bm * 64 + m0 + g;
#pragma unroll
    for (int nt = 0; nt < 4; nt++) {
        const int col = bn * 64 + n0 + nt * 8 + cc * 2;
        *(float2*)&Y[row0 * DM + col] = make_float2(acc[nt][0], acc[nt][1]);
        *(float2*)&Y[(row0 + 8) * DM + col] = make_float2(acc[nt][2], acc[nt][3]);
    }
#undef ISSUE_CHUNK
}

// ---------------- tropical linear + partial reduce + activation ---------------
__global__ __launch_bounds__(256) void k_trop(const float* __restrict__ Wqt,
                                              const float* __restrict__ Wkt,
                                              const float* __restrict__ Wvt,
                                              const float* __restrict__ lam)
{
    __shared__ float Wts[64][65];
    __shared__ float ar[16][65];

    const int gemm = blockIdx.z;
    const float* Wt = (gemm == 0) ? Wqt : ((gemm == 1) ? Wkt : Wvt);
    float* out = (gemm == 0) ? g_Q : ((gemm == 1) ? g_K : g_V);
    const int bh = blockIdx.y;
    const int b = bh >> 3, h = bh & 7;
    const int l0 = blockIdx.x * 16;
    const int tid = threadIdx.x;

    for (int idx = tid; idx < 64 * 64; idx += 256) {
        const int o = idx >> 6, i = idx & 63;
        Wts[i][o] = Wt[idx];
    }
    for (int idx = tid; idx < 16 * 64; idx += 256) {
        const int r = idx >> 6, i = idx & 63;
        const int gidx = (b * LSEQ + l0 + r) * DM + h * DK + i;
        const float* p = g_pp + gemm * 2 * (BL * DM) + gidx;
        const float s = p[0] + p[BL * DM];
        ar[r][i] = log1pf(fmaxf(s, 0.0f)) - lam[h * DK + i];
    }
    __syncthreads();

    const int o = tid & 63, rg = tid >> 6;
    float m[4] = {NEG_BIG, NEG_BIG, NEG_BIG, NEG_BIG};
#pragma unroll 8
    for (int i = 0; i < 64; i++) {
        const float wv = Wts[i][o];
#pragma unroll
        for (int rr = 0; rr < 4; rr++)
            m[rr] = fmaxf(m[rr], ar[rg * 4 + rr][i] + wv);
    }
#pragma unroll
    for (int rr = 0; rr < 4; rr++)
        out[(bh * LSEQ + l0 + rg * 4 + rr) * DK + o] = m[rr];
}

// ---------------- fused tropical attention (low-LDS v2) -----------------------
// i-tile 16, grid (16, 16), 256 threads. 4 chunks of 64 j.
// phase A: per-thread 2i x 2j (Q broadcast, K transposed), phase B: 2i x 2d.
__global__ __launch_bounds__(256, 2) void k_attn(float* __restrict__ scores)
{
    __shared__ float Qs[16][68];
    __shared__ float Kt[64][66];   // transposed: Kt[d][j]
    __shared__ float Vs[64][68];
    __shared__ float Ss[64][17];   // [j][i]

    const int bh = blockIdx.y;
    const int it = blockIdx.x;        // 0..15
    const int i0 = it * 16;
    const int b = bh >> 3, h = bh & 7;
    const int tid = threadIdx.x;
    const int lane = tid & 31;
    const int wg = tid >> 5;          // warp 0..7
    const int ia = wg * 2;            // this thread's 2 i rows (both phases)
    const int ja = lane * 2;          // phase-A 2 j cols

    // load Q tile (16 x 64)
    {
        const int r = tid >> 4, dq = (tid & 15) * 4;
        *(float4*)&Qs[r][dq] = *(const float4*)&g_Q[(bh * LSEQ + i0 + r) * DK + dq];
    }

    float acc[2][2];
#pragma unroll
    for (int a = 0; a < 2; a++)
#pragma unroll
        for (int d = 0; d < 2; d++) acc[a][d] = NEG_BIG;

    for (int c = 0; c < 4; c++) {
        const float4* Kp = (const float4*)(g_K + (bh * LSEQ + c * 64) * DK);
        const float4* Vp = (const float4*)(g_V + (bh * LSEQ + c * 64) * DK);
        for (int idx = tid; idx < 1024; idx += 256) {
            const int j = idx >> 4, q4 = idx & 15, d4 = q4 * 4;
            const float4 kv = Kp[j * 16 + q4];
            Kt[d4 + 0][j] = kv.x; Kt[d4 + 1][j] = kv.y;
            Kt[d4 + 2][j] = kv.z; Kt[d4 + 3][j] = kv.w;
            *(float4*)&Vs[j][d4] = Vp[j * 16 + q4];
        }
        __syncthreads();

        // ---- phase A: 2i x 2j scores ----
        {
            float mx00 = NEG_BIG, mx01 = NEG_BIG, mx10 = NEG_BIG, mx11 = NEG_BIG;
            float mn00 = POS_BIG, mn01 = POS_BIG, mn10 = POS_BIG, mn11 = POS_BIG;
#pragma unroll
            for (int t = 0; t < 16; t++) {
                const float4 q0 = *(const float4*)&Qs[ia][t * 4];      // broadcast
                const float4 q1 = *(const float4*)&Qs[ia + 1][t * 4];  // broadcast
#pragma unroll
                for (int e = 0; e < 4; e++) {
                    const float2 kd = *(const float2*)&Kt[t * 4 + e][ja];
                    const float q0e = (e == 0) ? q0.x : (e == 1) ? q0.y : (e == 2) ? q0.z : q0.w;
                    const float q1e = (e == 0) ? q1.x : (e == 1) ? q1.y : (e == 2) ? q1.z : q1.w;
                    const float d00 = q0e - kd.x;
                    const float d01 = q0e - kd.y;
                    const float d10 = q1e - kd.x;
                    const float d11 = q1e - kd.y;
                    mx00 = fmaxf(mx00, d00); mn00 = fminf(mn00, d00);
                    mx01 = fmaxf(mx01, d01); mn01 = fminf(mn01, d01);
                    mx10 = fmaxf(mx10, d10); mn10 = fminf(mn10, d10);
                    mx11 = fmaxf(mx11, d11); mn11 = fminf(mn11, d11);
                }
            }
            const float s00 = mn00 - mx00, s01 = mn01 - mx01;
            const float s10 = mn10 - mx10, s11 = mn11 - mx11;
            // global store (coalesced float2 per row)
            float* g0 = &scores[(bh * LSEQ + i0 + ia) * LSEQ + c * 64 + ja];
            float* g1 = &scores[(bh * LSEQ + i0 + ia + 1) * LSEQ + c * 64 + ja];
            *(float2*)g0 = make_float2(s00, s01);
            *(float2*)g1 = make_float2(s10, s11);
            // smem tile for phase B
            Ss[ja][ia] = s00;     Ss[ja + 1][ia] = s01;
            Ss[ja][ia + 1] = s10; Ss[ja + 1][ia + 1] = s11;
        }
        __syncthreads();

        // ---- phase B: 2i x 2d context ----
        const int d0 = lane * 2;
#pragma unroll 4
        for (int j = 0; j < 64; j += 2) {
            const float2 v0 = *(const float2*)&Vs[j][d0];
            const float2 v1 = *(const float2*)&Vs[j + 1][d0];
            const float sa0 = Ss[j][ia], sa1 = Ss[j][ia + 1];          // broadcast
            const float sb0 = Ss[j + 1][ia], sb1 = Ss[j + 1][ia + 1];  // broadcast
            acc[0][0] = fmaxf(acc[0][0], sa0 + v0.x);
            acc[0][1] = fmaxf(acc[0][1], sa0 + v0.y);
            acc[1][0] = fmaxf(acc[1][0], sa1 + v0.x);
            acc[1][1] = fmaxf(acc[1][1], sa1 + v0.y);
            acc[0][0] = fmaxf(acc[0][0], sb0 + v1.x);
            acc[0][1] = fmaxf(acc[0][1], sb0 + v1.y);
            acc[1][0] = fmaxf(acc[1][0], sb1 + v1.x);
            acc[1][1] = fmaxf(acc[1][1], sb1 + v1.y);
        }
        __syncthreads();
    }

    // write split ctx
#pragma unroll
    for (int a = 0; a < 2; a++) {
        const int l = i0 + ia + a;
        const float vx = expm1f(acc[a][0]);
        const float vy = expm1f(acc[a][1]);
        const float hx = tf32r(vx), hy = tf32r(vy);
        *(float4*)&g_ctxs[(b * LSEQ + l) * DM + h * DK + lane * 2] =
            make_float4(hx, tf32r(vx - hx), hy, tf32r(vy - hy));
    }
}

// ---------------- splitK reduce for the output GEMM ---------------------------
__global__ __launch_bounds__(256) void k_reduce(float* __restrict__ out)
{
    const int idx = blockIdx.x * 256 + threadIdx.x;
    const float4* p = (const float4*)g_op;
    float4 s = p[idx];
#pragma unroll
    for (int z = 1; z < 4; z++) {
        const float4 t = p[z * 65536 + idx];
        s.x += t.x; s.y += t.y; s.z += t.z; s.w += t.w;
    }
    ((float4*)out)[idx] = s;
}

// ---------------- launch ------------------------------------------------------
extern "C" void kernel_launch(void* const* d_in, const int* in_sizes, int n_in,
                              void* d_out, int out_size)
{
    const float* x   = (const float*)d_in[0];
    const float* Wq  = (const float*)d_in[1];
    const float* Wk  = (const float*)d_in[2];
    const float* Wv  = (const float*)d_in[3];
    const float* Wo  = (const float*)d_in[4];
    const float* lam = (const float*)d_in[5];
    const float* Wqt = (const float*)d_in[6];
    const float* Wkt = (const float*)d_in[7];
    const float* Wvt = (const float*)d_in[8];
    float* out = (float*)d_out;
    float* scores = out + BL * DM;

    k_split<<<dim3(128, 5), 256>>>(x, Wq, Wk, Wv, Wo);
    k_gemm_tc<<<dim3(8, 8, 6), 256>>>(0);
    k_trop<<<dim3(16, 16, 3), 256>>>(Wqt, Wkt, Wvt, lam);
    k_attn<<<dim3(16, 16), 256>>>(scores);
    k_gemm_tc<<<dim3(8, 8, 4), 256>>>(1);
    k_reduce<<<256, 256>>>(out);
}